// round 5
// baseline (speedup 1.0000x reference)
#include <cuda_runtime.h>
#include <cstdint>

#define P_  128
#define D_  128
#define R_  16384
#define E_  131072
#define T_  1024
#define F_  513
#define FP_ 520     // padded row stride in float2 (16B-aligned rows)
#define KT_ 32      // k-chunk for GEMM

// ---------------- scratch (static device allocations; no cudaMalloc) ----------
static __device__ float2 g_bufA[R_*FP_ + 256];   // r_k   (SpMM output / GEMM input)
static __device__ float2 g_bufB[R_*FP_ + 256];   // tmp = prop * (K r)  (GEMM out / SpMM in)
static __device__ float  g_K[P_*D_*D_];          // K stored [p][e][d]  (e = contraction)
static __device__ __align__(16) int g_rowptr[R_+4];
static __device__ __align__(16) int g_rowcnt[R_];
static __device__ int    g_cols[E_];
static __device__ float  g_vals[E_];
static __device__ float  g_echo[2*F_];
static __device__ float  g_time[T_];

// ---------------- constants matching reference fp32 rounding ------------------
__device__ __forceinline__ float c_s32()  { return (float)(16000.0/343.0); }                 // SR/C
__device__ __forceinline__ float c_c32()  { return (float)(-2.0*3.14159265358979323846/1024.0); }
__device__ __forceinline__ float c_kdec() { return (float)(-6.907755278982137/343.0 - 0.001); }
#define LOG_GAMMA_F (-6.907755278982137f)

// sin/cos of x (|x| up to ~5000) with 2-term Cody-Waite reduction mod 2pi.
__device__ __forceinline__ void sc_big(float x, float& s, float& c) {
    float k = rintf(x * 0.15915494309189535f);
    float r = fmaf(k, -6.28125f, x);                  // exact (k<2^10, 9-bit C1)
    r = fmaf(k, -1.9353071795864769e-3f, r);
    __sincosf(r, &s, &c);
}

// packed f32x2 helpers
__device__ __forceinline__ unsigned long long pk2(float k) {
    unsigned long long r;
    asm("mov.b64 %0, {%1, %1};" : "=l"(r) : "f"(k));
    return r;
}
__device__ __forceinline__ unsigned long long fma2(unsigned long long a, unsigned long long b,
                                                   unsigned long long c) {
    unsigned long long d;
    asm("fma.rn.f32x2 %0, %1, %2, %3;" : "=l"(d) : "l"(a), "l"(b), "l"(c));
    return d;
}
__device__ __forceinline__ float lo32(unsigned long long v) { return __uint_as_float((unsigned)(v & 0xffffffffull)); }
__device__ __forceinline__ float hi32(unsigned long long v) { return __uint_as_float((unsigned)(v >> 32)); }

// ---------------- setup: build K, zero echo/time/rowcnt (fused) ---------------
__global__ void k_buildKzero(const float* __restrict__ basis, const float* __restrict__ absorb,
                             const float* __restrict__ scat, const int* __restrict__ obj) {
    int idx = blockIdx.x * blockDim.x + threadIdx.x;
    if (idx < 2*F_) g_echo[idx] = 0.0f;
    if (idx < T_)   g_time[idx] = 0.0f;
    if (idx < R_)   g_rowcnt[idx] = 0;
    if (idx >= P_*D_*D_) return;
    int p = idx / (D_*D_);
    int rem = idx - p*D_*D_;
    int e = rem / D_;
    int d = rem - e*D_;
    int o = obj[p];
    float refl = 1.0f - absorb[o];
    float c0 = refl * scat[o];
    float c1 = refl * (1.0f - scat[o]);
    // K[p,d,e] = c0*B0[d,e] + c1*B1[d,e]; stored transposed as g_K[p][e][d]
    g_K[idx] = c0 * basis[d*D_ + e] + c1 * basis[D_*D_ + d*D_ + e];
}

__global__ void k_hist(const int* __restrict__ gkr) {
    int e = blockIdx.x * blockDim.x + threadIdx.x;
    if (e < E_) atomicAdd(&g_rowcnt[gkr[e]], 1);
}

// single block, 1024 threads, 16 values each: int4 loads + shuffle scan
__global__ void __launch_bounds__(1024) k_scan() {
    __shared__ int wsum[32];
    int t = threadIdx.x, lane = t & 31, wid = t >> 5;
    int4 v[4];
    const int4* src = (const int4*)g_rowcnt;
#pragma unroll
    for (int i = 0; i < 4; i++) v[i] = src[t*4 + i];
    const int* x = (const int*)v;
    int loc[16], sum = 0;
#pragma unroll
    for (int i = 0; i < 16; i++) { loc[i] = sum; sum += x[i]; }
    int incl = sum;
#pragma unroll
    for (int off = 1; off < 32; off <<= 1) {
        int n = __shfl_up_sync(0xffffffffu, incl, off);
        if (lane >= off) incl += n;
    }
    if (lane == 31) wsum[wid] = incl;
    __syncthreads();
    if (wid == 0) {
        int ws = wsum[lane];
#pragma unroll
        for (int off = 1; off < 32; off <<= 1) {
            int n = __shfl_up_sync(0xffffffffu, ws, off);
            if (lane >= off) ws += n;
        }
        wsum[lane] = ws;
    }
    __syncthreads();
    int off0 = (wid > 0 ? wsum[wid-1] : 0) + (incl - sum);
    int4 o[4];
    int* op = (int*)o;
#pragma unroll
    for (int i = 0; i < 16; i++) op[i] = off0 + loc[i];
    int4* dst = (int4*)g_rowptr;
    int4* cz  = (int4*)g_rowcnt;
    int4 z = make_int4(0,0,0,0);
#pragma unroll
    for (int i = 0; i < 4; i++) { dst[t*4 + i] = o[i]; cz[t*4 + i] = z; }
    if (t == 1023) g_rowptr[R_] = wsum[31];
}

__global__ void k_scatter(const int* __restrict__ gkr, const int* __restrict__ gkc,
                          const float* __restrict__ gkv) {
    int e = blockIdx.x * blockDim.x + threadIdx.x;
    if (e >= E_) return;
    int r = gkr[e];
    int pos = g_rowptr[r] + atomicAdd(&g_rowcnt[r], 1);
    g_cols[pos] = gkc[e];
    g_vals[pos] = gkv[e];
}

// ---------------- rad: bufA = rad, echo += w_rec*pf_rec*rad -------------------
__global__ void __launch_bounds__(256) k_rad(const float* __restrict__ rpos,
                                             const float* __restrict__ spos,
                                             const float* __restrict__ rcpos) {
    __shared__ float2 esh[8][516];
    int w = threadIdx.x >> 5, lane = threadIdx.x & 31;
    int row = blockIdx.x * 8 + w;

    float px = rpos[3*row+0], py = rpos[3*row+1], pz = rpos[3*row+2];
    float dx = px - spos[0], dy = py - spos[1], dz = pz - spos[2];
    float ds = sqrtf(dx*dx + dy*dy + dz*dz);
    float bs = c_c32() * (ds * c_s32());
    float amp = __expf(c_kdec() * ds) / (ds*ds + 0.001f);

    float rx = px - rcpos[0], ry = py - rcpos[1], rz = pz - rcpos[2];
    float dr = sqrtf(rx*rx + ry*ry + rz*rz);
    float br = c_c32() * (dr * c_s32());
    float wamp = __expf(c_kdec() * dr) / (dr*dr + 0.001f);

#pragma unroll
    for (int k = 0; k < 16; k++) {
        int f = k*32 + lane;
        float s1, c1; sc_big(bs * (float)f, s1, c1);
        float2 rad = make_float2(amp * c1, amp * s1);
        g_bufA[(size_t)row*FP_ + f] = rad;
        float s2, c2; sc_big(br * (float)f, s2, c2);
        esh[w][f] = make_float2(wamp * (c2*rad.x - s2*rad.y), wamp * (c2*rad.y + s2*rad.x));
    }
    if (lane == 0) {
        float s1, c1; sc_big(bs * 512.0f, s1, c1);
        float2 rad = make_float2(amp * c1, amp * s1);
        g_bufA[(size_t)row*FP_ + 512] = rad;
        float s2, c2; sc_big(br * 512.0f, s2, c2);
        esh[w][512] = make_float2(wamp * (c2*rad.x - s2*rad.y), wamp * (c2*rad.y + s2*rad.x));
    }
    __syncthreads();
    for (int f = threadIdx.x; f < F_; f += 256) {
        float sr = 0.0f, si = 0.0f;
#pragma unroll
        for (int ww = 0; ww < 8; ww++) { sr += esh[ww][f].x; si += esh[ww][f].y; }
        atomicAdd(&g_echo[2*f  ], sr);
        atomicAdd(&g_echo[2*f+1], si);
    }
}

// ---------------- GEMM: bufB = prop * (K_p @ bufA), packed f32x2 --------------
// grid (P_, 8): block tile 128d x 64f; thread tile 4d x 8f; 2 blocks/SM.
__global__ void __launch_bounds__(256, 2) k_gemm(const float* __restrict__ avg_dist) {
    __shared__ float  Ks[KT_][128];      // [e][d]
    __shared__ float2 Xs[KT_][64];       // [e][f]
    int p  = blockIdx.x;
    int ft = blockIdx.y;
    int tid = threadIdx.x;
    int tf = tid & 7, td = tid >> 3;     // 8 f-groups x 8f, 32 d-groups x 4d
    int f0 = ft * 64;

    unsigned long long acc[32];          // [4 d][8 f]
#pragma unroll
    for (int i = 0; i < 32; i++) acc[i] = 0ull;

    const float*  Kp    = g_K + (size_t)p * D_ * D_;
    const float2* xbase = g_bufA + (size_t)(p*128) * FP_ + f0;

    for (int c = 0; c < 128; c += KT_) {
        // K chunk: 4096 floats = 1024 float4; 256 threads -> 4 each
        {
            const float4* src = (const float4*)(Kp + c*128);
            float4* dst = (float4*)&Ks[0][0];
#pragma unroll
            for (int i = 0; i < 4; i++) dst[tid + 256*i] = src[tid + 256*i];
        }
        // X chunk: 32 rows x 32 float4 = 1024 float4 -> 4 each
#pragma unroll
        for (int i = 0; i < 4; i++) {
            int lin = tid + 256*i;
            int kk = lin >> 5, f4 = lin & 31;
            const float4* s = (const float4*)(xbase + (size_t)(c + kk) * FP_);
            ((float4*)&Xs[kk][0])[f4] = s[f4];
        }
        __syncthreads();
#pragma unroll 4
        for (int kk = 0; kk < KT_; kk++) {
            float4 ka = *(const float4*)&Ks[kk][td*4];
            const ulonglong2* xp = (const ulonglong2*)&Xs[kk][tf*8];
            ulonglong2 x01 = xp[0], x23 = xp[1], x45 = xp[2], x67 = xp[3];
            unsigned long long xv[8] = {x01.x, x01.y, x23.x, x23.y, x45.x, x45.y, x67.x, x67.y};
            unsigned long long kp[4] = {pk2(ka.x), pk2(ka.y), pk2(ka.z), pk2(ka.w)};
#pragma unroll
            for (int i = 0; i < 4; i++)
#pragma unroll
                for (int j = 0; j < 8; j++)
                    acc[i*8 + j] = fma2(kp[i], xv[j], acc[i*8 + j]);
        }
        __syncthreads();
    }

    int rowb = p*128 + td*4;
#pragma unroll
    for (int i = 0; i < 4; i++) {
        int row = rowb + i;
        float dist = avg_dist[row];
        float b = c_c32() * (dist * c_s32());
        float dec = __expf(c_kdec() * dist);
        float2* outp = g_bufB + (size_t)row*FP_ + f0 + tf*8;
#pragma unroll
        for (int j = 0; j < 8; j += 2) {
            int f = f0 + tf*8 + j;
            float ar0 = lo32(acc[i*8 + j]),   ai0 = hi32(acc[i*8 + j]);
            float ar1 = lo32(acc[i*8 + j+1]), ai1 = hi32(acc[i*8 + j+1]);
            float ss0, cc0; sc_big(b * (float)f, ss0, cc0);
            float ss1, cc1; sc_big(b * (float)(f+1), ss1, cc1);
            float pr0 = dec * cc0, pi0 = dec * ss0;
            float pr1 = dec * cc1, pi1 = dec * ss1;
            float4 st = make_float4(pr0*ar0 - pi0*ai0, pr0*ai0 + pi0*ar0,
                                    pr1*ar1 - pi1*ai1, pr1*ai1 + pi1*ar1);
            *(float4*)(outp + j) = st;
        }
    }
}

// f = 512 column only
__global__ void __launch_bounds__(128) k_gemm_last(const float* __restrict__ avg_dist) {
    __shared__ float2 xs[128];
    int p = blockIdx.x, d = threadIdx.x;
    xs[d] = g_bufA[(size_t)(p*128 + d)*FP_ + 512];
    __syncthreads();
    const float* Kp = g_K + (size_t)p * D_ * D_;
    float ar = 0.0f, ai = 0.0f;
#pragma unroll 8
    for (int e = 0; e < 128; e++) {
        float kv = Kp[e*128 + d];
        float2 x = xs[e];
        ar = fmaf(kv, x.x, ar);
        ai = fmaf(kv, x.y, ai);
    }
    int row = p*128 + d;
    float dist = avg_dist[row];
    float b = c_c32() * (dist * c_s32());
    float dec = __expf(c_kdec() * dist);
    float ss, cc; sc_big(b * 512.0f, ss, cc);
    float pr = dec * cc, pi = dec * ss;
    g_bufB[(size_t)row*FP_ + 512] = make_float2(pr*ar - pi*ai, pr*ai + pi*ar);
}

// ---------------- SpMM: bufA = A @ bufB, echo += w_rec*pf_rec*bufA ------------
__global__ void __launch_bounds__(256) k_spmm(const float* __restrict__ rpos,
                                              const float* __restrict__ rcpos) {
    __shared__ float2 esh[8][516];
    int w = threadIdx.x >> 5, lane = threadIdx.x & 31;
    int row = blockIdx.x * 8 + w;
    int s = g_rowptr[row], e = g_rowptr[row+1];

    float ar[17], ai[17];
#pragma unroll
    for (int k = 0; k < 17; k++) { ar[k] = 0.0f; ai[k] = 0.0f; }

    for (int j = s; j < e; j++) {
        int cj = g_cols[j];
        float vj = g_vals[j];
        const float2* __restrict__ base = g_bufB + (size_t)cj * FP_;
#pragma unroll
        for (int k = 0; k < 16; k++) {
            float2 t = base[k*32 + lane];
            ar[k] = fmaf(vj, t.x, ar[k]);
            ai[k] = fmaf(vj, t.y, ai[k]);
        }
        if (lane == 0) {
            float2 t = base[512];
            ar[16] = fmaf(vj, t.x, ar[16]);
            ai[16] = fmaf(vj, t.y, ai[16]);
        }
    }

    float px = rpos[3*row+0], py = rpos[3*row+1], pz = rpos[3*row+2];
    float rx = px - rcpos[0], ry = py - rcpos[1], rz = pz - rcpos[2];
    float dr = sqrtf(rx*rx + ry*ry + rz*rz);
    float br = c_c32() * (dr * c_s32());
    float wamp = __expf(c_kdec() * dr) / (dr*dr + 0.001f);

#pragma unroll
    for (int k = 0; k < 16; k++) {
        int f = k*32 + lane;
        g_bufA[(size_t)row*FP_ + f] = make_float2(ar[k], ai[k]);
        float s2, c2; sc_big(br * (float)f, s2, c2);
        esh[w][f] = make_float2(wamp * (c2*ar[k] - s2*ai[k]), wamp * (c2*ai[k] + s2*ar[k]));
    }
    if (lane == 0) {
        g_bufA[(size_t)row*FP_ + 512] = make_float2(ar[16], ai[16]);
        float s2, c2; sc_big(br * 512.0f, s2, c2);
        esh[w][512] = make_float2(wamp * (c2*ar[16] - s2*ai[16]), wamp * (c2*ai[16] + s2*ar[16]));
    }
    __syncthreads();
    for (int f = threadIdx.x; f < F_; f += 256) {
        float sr = 0.0f, si = 0.0f;
#pragma unroll
        for (int ww = 0; ww < 8; ww++) { sr += esh[ww][f].x; si += esh[ww][f].y; }
        atomicAdd(&g_echo[2*f  ], sr);
        atomicAdd(&g_echo[2*f+1], si);
    }
}

// ---------------- final: irfft(echo) / fsm_window -----------------------------
__global__ void __launch_bounds__(1024) k_ifft() {
    __shared__ float twc[T_], tws[T_];
    __shared__ float2 es[32];
    int t = threadIdx.x, b = blockIdx.x;
    {
        float th = (float)(2.0*3.14159265358979323846/1024.0) * (float)t;
        float s, c; __sincosf(th, &s, &c);
        twc[t] = c; tws[t] = s;
    }
    if (t < 32) {
        int k = b*32 + 1 + t;
        float2 v = make_float2(g_echo[2*k], g_echo[2*k+1]);
        if (k == 512) { v.x *= 0.5f; v.y *= 0.5f; }
        es[t] = v;
    }
    __syncthreads();
    float sum = 0.0f;
#pragma unroll 8
    for (int i = 0; i < 32; i++) {
        int k = b*32 + 1 + i;
        int m = (k * t) & 1023;
        float2 X = es[i];
        sum = fmaf(2.0f * X.x, twc[m], sum);
        sum = fmaf(-2.0f * X.y, tws[m], sum);
    }
    atomicAdd(&g_time[t], sum);
}

__global__ void __launch_bounds__(1024) k_scale(float* __restrict__ out) {
    int t = threadIdx.x;
    float v = (g_time[t] + g_echo[0]) * (1.0f / 1024.0f);
    float ta = (float)t / 16000.0f;
    float fsm = __expf(LOG_GAMMA_F * ta);
    out[t] = v / fsm;
}

// ---------------- launcher ----------------------------------------------------
extern "C" void kernel_launch(void* const* d_in, const int* in_sizes, int n_in,
                              void* d_out, int out_size) {
    const float* spos  = (const float*)d_in[0];
    const float* rcpos = (const float*)d_in[1];
    const float* absorb= (const float*)d_in[2];
    const float* scat  = (const float*)d_in[3];
    const float* gkv   = (const float*)d_in[4];
    const float* basis = (const float*)d_in[5];
    const float* avg   = (const float*)d_in[6];
    const float* rpos  = (const float*)d_in[7];
    const int*   gkr   = (const int*)d_in[8];
    const int*   gkc   = (const int*)d_in[9];
    const int*   obj   = (const int*)d_in[10];

    // Order chosen so launch #4 (what ncu -s captures) is the heavy k_gemm.
    k_buildKzero<<<(P_*D_*D_ + 255)/256, 256>>>(basis, absorb, scat, obj);  // 1
    k_hist<<<E_/256, 256>>>(gkr);                                           // 2
    k_rad<<<R_/8, 256>>>(rpos, spos, rcpos);                                // 3
    k_gemm<<<dim3(P_, 8), 256>>>(avg);                                      // 4  <- profile target
    k_scan<<<1, 1024>>>();                                                  // 5
    k_scatter<<<E_/256, 256>>>(gkr, gkc, gkv);                              // 6
    k_gemm_last<<<P_, 128>>>(avg);                                          // 7
    k_spmm<<<R_/8, 256>>>(rpos, rcpos);                                     // 8
    for (int b = 1; b < 4; b++) {
        k_gemm<<<dim3(P_, 8), 256>>>(avg);
        k_gemm_last<<<P_, 128>>>(avg);
        k_spmm<<<R_/8, 256>>>(rpos, rcpos);
    }
    k_ifft<<<16, 1024>>>();
    k_scale<<<1, 1024>>>((float*)d_out);
}

// round 6
// speedup vs baseline: 1.6967x; 1.6967x over previous
#include <cuda_runtime.h>
#include <cstdint>

#define P_  128
#define D_  128
#define R_  16384
#define E_  131072
#define T_  1024
#define F_  513
#define FP_ 520     // padded row stride in float2 (16B-aligned rows)
#define KT_ 32      // k-chunk for GEMM

// ---------------- scratch (static device allocations; no cudaMalloc) ----------
static __device__ float2 g_bufA[R_*FP_ + 256];   // r_k   (SpMM output / GEMM input)
static __device__ float2 g_bufB[R_*FP_ + 256];   // tmp = prop * (K r)  (GEMM out / SpMM in)
static __device__ float  g_K[P_*D_*D_];          // K stored [p][e][d]  (e = contraction)
static __device__ __align__(16) int g_rowptr[R_+4];
static __device__ __align__(16) int g_rowcnt[R_];
static __device__ int    g_cols[E_];
static __device__ float  g_vals[E_];
static __device__ float  g_echo[2*F_];
static __device__ float  g_time[T_];

// ---------------- constants matching reference fp32 rounding ------------------
__device__ __forceinline__ float c_s32()  { return (float)(16000.0/343.0); }                 // SR/C
__device__ __forceinline__ float c_c32()  { return (float)(-2.0*3.14159265358979323846/1024.0); }
__device__ __forceinline__ float c_kdec() { return (float)(-6.907755278982137/343.0 - 0.001); }
#define LOG_GAMMA_F (-6.907755278982137f)

// sin/cos of x (|x| up to ~5000) with 2-term Cody-Waite reduction mod 2pi.
__device__ __forceinline__ void sc_big(float x, float& s, float& c) {
    float k = rintf(x * 0.15915494309189535f);
    float r = fmaf(k, -6.28125f, x);                  // exact (k<2^10, 9-bit C1)
    r = fmaf(k, -1.9353071795864769e-3f, r);
    __sincosf(r, &s, &c);
}

// packed f32x2 helpers
__device__ __forceinline__ unsigned long long pk2(float k) {
    unsigned long long r;
    asm("mov.b64 %0, {%1, %1};" : "=l"(r) : "f"(k));
    return r;
}
__device__ __forceinline__ unsigned long long fma2(unsigned long long a, unsigned long long b,
                                                   unsigned long long c) {
    unsigned long long d;
    asm("fma.rn.f32x2 %0, %1, %2, %3;" : "=l"(d) : "l"(a), "l"(b), "l"(c));
    return d;
}
__device__ __forceinline__ float lo32(unsigned long long v) { return __uint_as_float((unsigned)(v & 0xffffffffull)); }
__device__ __forceinline__ float hi32(unsigned long long v) { return __uint_as_float((unsigned)(v >> 32)); }

// ---------------- setup: build K, zero echo/time/rowcnt (fused) ---------------
__global__ void k_buildKzero(const float* __restrict__ basis, const float* __restrict__ absorb,
                             const float* __restrict__ scat, const int* __restrict__ obj) {
    int idx = blockIdx.x * blockDim.x + threadIdx.x;
    if (idx < 2*F_) g_echo[idx] = 0.0f;
    if (idx < T_)   g_time[idx] = 0.0f;
    if (idx < R_)   g_rowcnt[idx] = 0;
    if (idx >= P_*D_*D_) return;
    int p = idx / (D_*D_);
    int rem = idx - p*D_*D_;
    int e = rem / D_;
    int d = rem - e*D_;
    int o = obj[p];
    float refl = 1.0f - absorb[o];
    float c0 = refl * scat[o];
    float c1 = refl * (1.0f - scat[o]);
    // K[p,d,e] = c0*B0[d,e] + c1*B1[d,e]; stored transposed as g_K[p][e][d]
    g_K[idx] = c0 * basis[d*D_ + e] + c1 * basis[D_*D_ + d*D_ + e];
}

__global__ void k_hist(const int* __restrict__ gkr) {
    int e = blockIdx.x * blockDim.x + threadIdx.x;
    if (e < E_) atomicAdd(&g_rowcnt[gkr[e]], 1);
}

// single block, 1024 threads, 16 values each: int4 loads + shuffle scan
__global__ void __launch_bounds__(1024) k_scan() {
    __shared__ int wsum[32];
    int t = threadIdx.x, lane = t & 31, wid = t >> 5;
    int4 v[4];
    const int4* src = (const int4*)g_rowcnt;
#pragma unroll
    for (int i = 0; i < 4; i++) v[i] = src[t*4 + i];
    const int* x = (const int*)v;
    int loc[16], sum = 0;
#pragma unroll
    for (int i = 0; i < 16; i++) { loc[i] = sum; sum += x[i]; }
    int incl = sum;
#pragma unroll
    for (int off = 1; off < 32; off <<= 1) {
        int n = __shfl_up_sync(0xffffffffu, incl, off);
        if (lane >= off) incl += n;
    }
    if (lane == 31) wsum[wid] = incl;
    __syncthreads();
    if (wid == 0) {
        int ws = wsum[lane];
#pragma unroll
        for (int off = 1; off < 32; off <<= 1) {
            int n = __shfl_up_sync(0xffffffffu, ws, off);
            if (lane >= off) ws += n;
        }
        wsum[lane] = ws;
    }
    __syncthreads();
    int off0 = (wid > 0 ? wsum[wid-1] : 0) + (incl - sum);
    int4 o[4];
    int* op = (int*)o;
#pragma unroll
    for (int i = 0; i < 16; i++) op[i] = off0 + loc[i];
    int4* dst = (int4*)g_rowptr;
    int4* cz  = (int4*)g_rowcnt;
    int4 z = make_int4(0,0,0,0);
#pragma unroll
    for (int i = 0; i < 4; i++) { dst[t*4 + i] = o[i]; cz[t*4 + i] = z; }
    if (t == 1023) g_rowptr[R_] = wsum[31];
}

__global__ void k_scatter(const int* __restrict__ gkr, const int* __restrict__ gkc,
                          const float* __restrict__ gkv) {
    int e = blockIdx.x * blockDim.x + threadIdx.x;
    if (e >= E_) return;
    int r = gkr[e];
    int pos = g_rowptr[r] + atomicAdd(&g_rowcnt[r], 1);
    g_cols[pos] = gkc[e];
    g_vals[pos] = gkv[e];
}

// ---------------- rad: bufA = rad, echo += w_rec*pf_rec*rad -------------------
__global__ void __launch_bounds__(256) k_rad(const float* __restrict__ rpos,
                                             const float* __restrict__ spos,
                                             const float* __restrict__ rcpos) {
    __shared__ float2 esh[8][516];
    int w = threadIdx.x >> 5, lane = threadIdx.x & 31;
    int row = blockIdx.x * 8 + w;

    float px = rpos[3*row+0], py = rpos[3*row+1], pz = rpos[3*row+2];
    float dx = px - spos[0], dy = py - spos[1], dz = pz - spos[2];
    float ds = sqrtf(dx*dx + dy*dy + dz*dz);
    float bs = c_c32() * (ds * c_s32());
    float amp = __expf(c_kdec() * ds) / (ds*ds + 0.001f);

    float rx = px - rcpos[0], ry = py - rcpos[1], rz = pz - rcpos[2];
    float dr = sqrtf(rx*rx + ry*ry + rz*rz);
    float br = c_c32() * (dr * c_s32());
    float wamp = __expf(c_kdec() * dr) / (dr*dr + 0.001f);

#pragma unroll
    for (int k = 0; k < 16; k++) {
        int f = k*32 + lane;
        float s1, c1; sc_big(bs * (float)f, s1, c1);
        float2 rad = make_float2(amp * c1, amp * s1);
        g_bufA[(size_t)row*FP_ + f] = rad;
        float s2, c2; sc_big(br * (float)f, s2, c2);
        esh[w][f] = make_float2(wamp * (c2*rad.x - s2*rad.y), wamp * (c2*rad.y + s2*rad.x));
    }
    if (lane == 0) {
        float s1, c1; sc_big(bs * 512.0f, s1, c1);
        float2 rad = make_float2(amp * c1, amp * s1);
        g_bufA[(size_t)row*FP_ + 512] = rad;
        float s2, c2; sc_big(br * 512.0f, s2, c2);
        esh[w][512] = make_float2(wamp * (c2*rad.x - s2*rad.y), wamp * (c2*rad.y + s2*rad.x));
    }
    __syncthreads();
    for (int f = threadIdx.x; f < F_; f += 256) {
        float sr = 0.0f, si = 0.0f;
#pragma unroll
        for (int ww = 0; ww < 8; ww++) { sr += esh[ww][f].x; si += esh[ww][f].y; }
        atomicAdd(&g_echo[2*f  ], sr);
        atomicAdd(&g_echo[2*f+1], si);
    }
}

// ---------------- GEMM: bufB = prop * (K_p @ bufA), packed f32x2 --------------
// grid (P_, 8): block tile 128d x 64f; thread tile 4d x 8f; 2 blocks/SM.
// X tile stored chunk-interleaved so compute LDS.128s are bank-conflict-free:
//   source float4 chunk c (= tf*4+q) of row kk lives at slot q*8+tf.
//   Load q: lanes tf=0..7 read 8 consecutive 16B chunks -> 32 distinct banks.
__global__ void __launch_bounds__(256, 2) k_gemm(const float* __restrict__ avg_dist) {
    __shared__ float  Ks[KT_][128];        // [e][d]
    __shared__ float4 Xs[KT_*32];          // [e][slot] chunk-interleaved
    int p  = blockIdx.x;
    int ft = blockIdx.y;
    int tid = threadIdx.x;
    int tf = tid & 7, td = tid >> 3;       // 8 f-groups x 8f, 32 d-groups x 4d
    int f0 = ft * 64;

    unsigned long long acc[32];            // [4 d][8 f]
#pragma unroll
    for (int i = 0; i < 32; i++) acc[i] = 0ull;

    const float*  Kp    = g_K + (size_t)p * D_ * D_;
    const float2* xbase = g_bufA + (size_t)(p*128) * FP_ + f0;

    // per-thread staging source permutation (constant across chunks)
    int spos = tid & 31;                   // storage slot
    int stf  = spos & 7, sq = spos >> 3;
    int sc   = stf*4 + sq;                 // source float4 chunk index in row

    for (int c = 0; c < 128; c += KT_) {
        // K chunk: 4096 floats = 1024 float4; 256 threads -> 4 each (linear)
        {
            const float4* src = (const float4*)(Kp + c*128);
            float4* dst = (float4*)&Ks[0][0];
#pragma unroll
            for (int i = 0; i < 4; i++) dst[tid + 256*i] = src[tid + 256*i];
        }
        // X chunk: 32 rows x 32 float4, permuted placement
#pragma unroll
        for (int i = 0; i < 4; i++) {
            int lin = tid + 256*i;
            int kk = lin >> 5;
            const float4* s = (const float4*)(xbase + (size_t)(c + kk) * FP_);
            Xs[kk*32 + spos] = s[sc];
        }
        __syncthreads();
#pragma unroll 4
        for (int kk = 0; kk < KT_; kk++) {
            float4 ka = *(const float4*)&Ks[kk][td*4];
            const ulonglong2* xrow = (const ulonglong2*)&Xs[kk*32];
            ulonglong2 x01 = xrow[0*8 + tf];
            ulonglong2 x23 = xrow[1*8 + tf];
            ulonglong2 x45 = xrow[2*8 + tf];
            ulonglong2 x67 = xrow[3*8 + tf];
            unsigned long long xv[8] = {x01.x, x01.y, x23.x, x23.y, x45.x, x45.y, x67.x, x67.y};
            unsigned long long kp[4] = {pk2(ka.x), pk2(ka.y), pk2(ka.z), pk2(ka.w)};
#pragma unroll
            for (int i = 0; i < 4; i++)
#pragma unroll
                for (int j = 0; j < 8; j++)
                    acc[i*8 + j] = fma2(kp[i], xv[j], acc[i*8 + j]);
        }
        __syncthreads();
    }

    int rowb = p*128 + td*4;
#pragma unroll
    for (int i = 0; i < 4; i++) {
        int row = rowb + i;
        float dist = avg_dist[row];
        float b = c_c32() * (dist * c_s32());
        float dec = __expf(c_kdec() * dist);
        float2* outp = g_bufB + (size_t)row*FP_ + f0 + tf*8;
#pragma unroll
        for (int j = 0; j < 8; j += 2) {
            int f = f0 + tf*8 + j;
            float ar0 = lo32(acc[i*8 + j]),   ai0 = hi32(acc[i*8 + j]);
            float ar1 = lo32(acc[i*8 + j+1]), ai1 = hi32(acc[i*8 + j+1]);
            float ss0, cc0; sc_big(b * (float)f, ss0, cc0);
            float ss1, cc1; sc_big(b * (float)(f+1), ss1, cc1);
            float pr0 = dec * cc0, pi0 = dec * ss0;
            float pr1 = dec * cc1, pi1 = dec * ss1;
            float4 st = make_float4(pr0*ar0 - pi0*ai0, pr0*ai0 + pi0*ar0,
                                    pr1*ar1 - pi1*ai1, pr1*ai1 + pi1*ar1);
            *(float4*)(outp + j) = st;
        }
    }
}

// f = 512 column only
__global__ void __launch_bounds__(128) k_gemm_last(const float* __restrict__ avg_dist) {
    __shared__ float2 xs[128];
    int p = blockIdx.x, d = threadIdx.x;
    xs[d] = g_bufA[(size_t)(p*128 + d)*FP_ + 512];
    __syncthreads();
    const float* Kp = g_K + (size_t)p * D_ * D_;
    float ar = 0.0f, ai = 0.0f;
#pragma unroll 8
    for (int e = 0; e < 128; e++) {
        float kv = Kp[e*128 + d];
        float2 x = xs[e];
        ar = fmaf(kv, x.x, ar);
        ai = fmaf(kv, x.y, ai);
    }
    int row = p*128 + d;
    float dist = avg_dist[row];
    float b = c_c32() * (dist * c_s32());
    float dec = __expf(c_kdec() * dist);
    float ss, cc; sc_big(b * 512.0f, ss, cc);
    float pr = dec * cc, pi = dec * ss;
    g_bufB[(size_t)row*FP_ + 512] = make_float2(pr*ar - pi*ai, pr*ai + pi*ar);
}

// ---------------- SpMM: bufA = A @ bufB, echo += w_rec*pf_rec*bufA ------------
__global__ void __launch_bounds__(256) k_spmm(const float* __restrict__ rpos,
                                              const float* __restrict__ rcpos) {
    __shared__ float2 esh[8][516];
    int w = threadIdx.x >> 5, lane = threadIdx.x & 31;
    int row = blockIdx.x * 8 + w;
    int s = g_rowptr[row], e = g_rowptr[row+1];

    float ar[17], ai[17];
#pragma unroll
    for (int k = 0; k < 17; k++) { ar[k] = 0.0f; ai[k] = 0.0f; }

    for (int j = s; j < e; j++) {
        int cj = g_cols[j];
        float vj = g_vals[j];
        const float2* __restrict__ base = g_bufB + (size_t)cj * FP_;
#pragma unroll
        for (int k = 0; k < 16; k++) {
            float2 t = base[k*32 + lane];
            ar[k] = fmaf(vj, t.x, ar[k]);
            ai[k] = fmaf(vj, t.y, ai[k]);
        }
        if (lane == 0) {
            float2 t = base[512];
            ar[16] = fmaf(vj, t.x, ar[16]);
            ai[16] = fmaf(vj, t.y, ai[16]);
        }
    }

    float px = rpos[3*row+0], py = rpos[3*row+1], pz = rpos[3*row+2];
    float rx = px - rcpos[0], ry = py - rcpos[1], rz = pz - rcpos[2];
    float dr = sqrtf(rx*rx + ry*ry + rz*rz);
    float br = c_c32() * (dr * c_s32());
    float wamp = __expf(c_kdec() * dr) / (dr*dr + 0.001f);

#pragma unroll
    for (int k = 0; k < 16; k++) {
        int f = k*32 + lane;
        g_bufA[(size_t)row*FP_ + f] = make_float2(ar[k], ai[k]);
        float s2, c2; sc_big(br * (float)f, s2, c2);
        esh[w][f] = make_float2(wamp * (c2*ar[k] - s2*ai[k]), wamp * (c2*ai[k] + s2*ar[k]));
    }
    if (lane == 0) {
        g_bufA[(size_t)row*FP_ + 512] = make_float2(ar[16], ai[16]);
        float s2, c2; sc_big(br * 512.0f, s2, c2);
        esh[w][512] = make_float2(wamp * (c2*ar[16] - s2*ai[16]), wamp * (c2*ai[16] + s2*ar[16]));
    }
    __syncthreads();
    for (int f = threadIdx.x; f < F_; f += 256) {
        float sr = 0.0f, si = 0.0f;
#pragma unroll
        for (int ww = 0; ww < 8; ww++) { sr += esh[ww][f].x; si += esh[ww][f].y; }
        atomicAdd(&g_echo[2*f  ], sr);
        atomicAdd(&g_echo[2*f+1], si);
    }
}

// ---------------- final: irfft(echo) / fsm_window -----------------------------
__global__ void __launch_bounds__(1024) k_ifft() {
    __shared__ float twc[T_], tws[T_];
    __shared__ float2 es[32];
    int t = threadIdx.x, b = blockIdx.x;
    {
        float th = (float)(2.0*3.14159265358979323846/1024.0) * (float)t;
        float s, c; __sincosf(th, &s, &c);
        twc[t] = c; tws[t] = s;
    }
    if (t < 32) {
        int k = b*32 + 1 + t;
        float2 v = make_float2(g_echo[2*k], g_echo[2*k+1]);
        if (k == 512) { v.x *= 0.5f; v.y *= 0.5f; }
        es[t] = v;
    }
    __syncthreads();
    float sum = 0.0f;
#pragma unroll 8
    for (int i = 0; i < 32; i++) {
        int k = b*32 + 1 + i;
        int m = (k * t) & 1023;
        float2 X = es[i];
        sum = fmaf(2.0f * X.x, twc[m], sum);
        sum = fmaf(-2.0f * X.y, tws[m], sum);
    }
    atomicAdd(&g_time[t], sum);
}

__global__ void __launch_bounds__(1024) k_scale(float* __restrict__ out) {
    int t = threadIdx.x;
    float v = (g_time[t] + g_echo[0]) * (1.0f / 1024.0f);
    float ta = (float)t / 16000.0f;
    float fsm = __expf(LOG_GAMMA_F * ta);
    out[t] = v / fsm;
}

// ---------------- launcher ----------------------------------------------------
extern "C" void kernel_launch(void* const* d_in, const int* in_sizes, int n_in,
                              void* d_out, int out_size) {
    const float* spos  = (const float*)d_in[0];
    const float* rcpos = (const float*)d_in[1];
    const float* absorb= (const float*)d_in[2];
    const float* scat  = (const float*)d_in[3];
    const float* gkv   = (const float*)d_in[4];
    const float* basis = (const float*)d_in[5];
    const float* avg   = (const float*)d_in[6];
    const float* rpos  = (const float*)d_in[7];
    const int*   gkr   = (const int*)d_in[8];
    const int*   gkc   = (const int*)d_in[9];
    const int*   obj   = (const int*)d_in[10];

    // Order chosen so launch #4 (what ncu -s captures) is the heavy k_gemm.
    k_buildKzero<<<(P_*D_*D_ + 255)/256, 256>>>(basis, absorb, scat, obj);  // 1
    k_hist<<<E_/256, 256>>>(gkr);                                           // 2
    k_rad<<<R_/8, 256>>>(rpos, spos, rcpos);                                // 3
    k_gemm<<<dim3(P_, 8), 256>>>(avg);                                      // 4  <- profile target
    k_scan<<<1, 1024>>>();                                                  // 5
    k_scatter<<<E_/256, 256>>>(gkr, gkc, gkv);                              // 6
    k_gemm_last<<<P_, 128>>>(avg);                                          // 7
    k_spmm<<<R_/8, 256>>>(rpos, rcpos);                                     // 8
    for (int b = 1; b < 4; b++) {
        k_gemm<<<dim3(P_, 8), 256>>>(avg);
        k_gemm_last<<<P_, 128>>>(avg);
        k_spmm<<<R_/8, 256>>>(rpos, rcpos);
    }
    k_ifft<<<16, 1024>>>();
    k_scale<<<1, 1024>>>((float*)d_out);
}

// round 8
// speedup vs baseline: 1.7276x; 1.0182x over previous
#include <cuda_runtime.h>
#include <cstdint>

#define P_  128
#define D_  128
#define R_  16384
#define E_  131072
#define T_  1024
#define F_  513
#define FP_ 520     // padded row stride in float2 (16B-aligned rows)
#define KT_ 32      // k-chunk for GEMM

// ---------------- scratch (static device allocations; no cudaMalloc) ----------
static __device__ __align__(16) float2 g_bufA[R_*FP_ + 256];   // r_k
static __device__ __align__(16) float2 g_bufB[R_*FP_ + 256];   // prop * (K r)
static __device__ __align__(16) float  g_K[P_*D_*D_];          // [p][e][d]
static __device__ __align__(16) int g_rowptr[R_+4];
static __device__ __align__(16) int g_rowcnt[R_];
static __device__ int    g_cols[E_];
static __device__ float  g_vals[E_];
static __device__ float  g_echo[2*F_];
static __device__ float  g_time[T_];

// ---------------- constants matching reference fp32 rounding ------------------
__device__ __forceinline__ float c_s32()  { return (float)(16000.0/343.0); }                 // SR/C
__device__ __forceinline__ float c_c32()  { return (float)(-2.0*3.14159265358979323846/1024.0); }
__device__ __forceinline__ float c_kdec() { return (float)(-6.907755278982137/343.0 - 0.001); }
#define LOG_GAMMA_F (-6.907755278982137f)

// sin/cos of x (|x| up to ~5000) with 2-term Cody-Waite reduction mod 2pi.
__device__ __forceinline__ void sc_big(float x, float& s, float& c) {
    float k = rintf(x * 0.15915494309189535f);
    float r = fmaf(k, -6.28125f, x);                  // exact (k<2^10, 9-bit C1)
    r = fmaf(k, -1.9353071795864769e-3f, r);
    __sincosf(r, &s, &c);
}

// packed f32x2 helpers
__device__ __forceinline__ unsigned long long pk2(float k) {
    unsigned long long r;
    asm("mov.b64 %0, {%1, %1};" : "=l"(r) : "f"(k));
    return r;
}
__device__ __forceinline__ unsigned long long fma2(unsigned long long a, unsigned long long b,
                                                   unsigned long long c) {
    unsigned long long d;
    asm("fma.rn.f32x2 %0, %1, %2, %3;" : "=l"(d) : "l"(a), "l"(b), "l"(c));
    return d;
}
__device__ __forceinline__ float lo32(unsigned long long v) { return __uint_as_float((unsigned)(v & 0xffffffffull)); }
__device__ __forceinline__ float hi32(unsigned long long v) { return __uint_as_float((unsigned)(v >> 32)); }

// ---------------- setup: build K, zero echo/time/rowcnt (fused) ---------------
__global__ void k_buildKzero(const float* __restrict__ basis, const float* __restrict__ absorb,
                             const float* __restrict__ scat, const int* __restrict__ obj) {
    int idx = blockIdx.x * blockDim.x + threadIdx.x;
    if (idx < 2*F_) g_echo[idx] = 0.0f;
    if (idx < T_)   g_time[idx] = 0.0f;
    if (idx < R_)   g_rowcnt[idx] = 0;
    if (idx >= P_*D_*D_) return;
    int p = idx / (D_*D_);
    int rem = idx - p*D_*D_;
    int e = rem / D_;
    int d = rem - e*D_;
    int o = obj[p];
    float refl = 1.0f - absorb[o];
    float c0 = refl * scat[o];
    float c1 = refl * (1.0f - scat[o]);
    g_K[idx] = c0 * basis[d*D_ + e] + c1 * basis[D_*D_ + d*D_ + e];
}

__global__ void k_hist(const int* __restrict__ gkr) {
    int e = blockIdx.x * blockDim.x + threadIdx.x;
    if (e < E_) atomicAdd(&g_rowcnt[gkr[e]], 1);
}

// single block, 1024 threads, 16 values each: int4 loads + shuffle scan
__global__ void __launch_bounds__(1024) k_scan() {
    __shared__ int wsum[32];
    int t = threadIdx.x, lane = t & 31, wid = t >> 5;
    int4 v[4];
    const int4* src = (const int4*)g_rowcnt;
#pragma unroll
    for (int i = 0; i < 4; i++) v[i] = src[t*4 + i];
    const int* x = (const int*)v;
    int loc[16], sum = 0;
#pragma unroll
    for (int i = 0; i < 16; i++) { loc[i] = sum; sum += x[i]; }
    int incl = sum;
#pragma unroll
    for (int off = 1; off < 32; off <<= 1) {
        int n = __shfl_up_sync(0xffffffffu, incl, off);
        if (lane >= off) incl += n;
    }
    if (lane == 31) wsum[wid] = incl;
    __syncthreads();
    if (wid == 0) {
        int ws = wsum[lane];
#pragma unroll
        for (int off = 1; off < 32; off <<= 1) {
            int n = __shfl_up_sync(0xffffffffu, ws, off);
            if (lane >= off) ws += n;
        }
        wsum[lane] = ws;
    }
    __syncthreads();
    int off0 = (wid > 0 ? wsum[wid-1] : 0) + (incl - sum);
    int4 o[4];
    int* op = (int*)o;
#pragma unroll
    for (int i = 0; i < 16; i++) op[i] = off0 + loc[i];
    int4* dst = (int4*)g_rowptr;
    int4* cz  = (int4*)g_rowcnt;
    int4 z = make_int4(0,0,0,0);
#pragma unroll
    for (int i = 0; i < 4; i++) { dst[t*4 + i] = o[i]; cz[t*4 + i] = z; }
    if (t == 1023) g_rowptr[R_] = wsum[31];
}

__global__ void k_scatter(const int* __restrict__ gkr, const int* __restrict__ gkc,
                          const float* __restrict__ gkv) {
    int e = blockIdx.x * blockDim.x + threadIdx.x;
    if (e >= E_) return;
    int r = gkr[e];
    int pos = g_rowptr[r] + atomicAdd(&g_rowcnt[r], 1);
    g_cols[pos] = gkc[e];
    g_vals[pos] = gkv[e];
}

// ---------------- rad: bufA = rad, echo += w_rec*pf_rec*rad -------------------
__global__ void __launch_bounds__(256) k_rad(const float* __restrict__ rpos,
                                             const float* __restrict__ spos,
                                             const float* __restrict__ rcpos) {
    __shared__ __align__(16) float2 esh[8][520];
    int w = threadIdx.x >> 5, lane = threadIdx.x & 31;
    int row = blockIdx.x * 8 + w;

    float px = rpos[3*row+0], py = rpos[3*row+1], pz = rpos[3*row+2];
    float dx = px - spos[0], dy = py - spos[1], dz = pz - spos[2];
    float ds = sqrtf(dx*dx + dy*dy + dz*dz);
    float bs = c_c32() * (ds * c_s32());
    float amp = __expf(c_kdec() * ds) / (ds*ds + 0.001f);

    float rx = px - rcpos[0], ry = py - rcpos[1], rz = pz - rcpos[2];
    float dr = sqrtf(rx*rx + ry*ry + rz*rz);
    float br = c_c32() * (dr * c_s32());
    float wamp = __expf(c_kdec() * dr) / (dr*dr + 0.001f);

#pragma unroll
    for (int k = 0; k < 16; k++) {
        int f = k*32 + lane;
        float s1, c1; sc_big(bs * (float)f, s1, c1);
        float2 rad = make_float2(amp * c1, amp * s1);
        g_bufA[(size_t)row*FP_ + f] = rad;
        float s2, c2; sc_big(br * (float)f, s2, c2);
        esh[w][f] = make_float2(wamp * (c2*rad.x - s2*rad.y), wamp * (c2*rad.y + s2*rad.x));
    }
    if (lane == 0) {
        float s1, c1; sc_big(bs * 512.0f, s1, c1);
        float2 rad = make_float2(amp * c1, amp * s1);
        g_bufA[(size_t)row*FP_ + 512] = rad;
        float s2, c2; sc_big(br * 512.0f, s2, c2);
        esh[w][512] = make_float2(wamp * (c2*rad.x - s2*rad.y), wamp * (c2*rad.y + s2*rad.x));
    }
    __syncthreads();
    for (int f = threadIdx.x; f < F_; f += 256) {
        float sr = 0.0f, si = 0.0f;
#pragma unroll
        for (int ww = 0; ww < 8; ww++) { sr += esh[ww][f].x; si += esh[ww][f].y; }
        atomicAdd(&g_echo[2*f  ], sr);
        atomicAdd(&g_echo[2*f+1], si);
    }
}

// ---------------- GEMM: bufB = prop * (K_p @ bufA), packed f32x2 --------------
// grid (P_, 8): block tile 128d x 64f. Warp w owns f-group w*8..w*8+7 (X is a
// 64B uniform broadcast per warp per kk); the 32 lanes split the 128 d-rows
// (K = one conflict-free LDS.128 per lane). Thread tile 4d x 8f, 2 blocks/SM.
__global__ void __launch_bounds__(256, 2) k_gemm(const float* __restrict__ avg_dist) {
    __shared__ float  Ks[KT_][128];      // [e][d]
    __shared__ float2 Xs[KT_][64];       // [e][f]  (64 float2 = 32 float4 per row)
    int p  = blockIdx.x;
    int ft = blockIdx.y;
    int tid = threadIdx.x;
    int w = tid >> 5, lane = tid & 31;
    int f0 = ft * 64;

    unsigned long long acc[32];          // [4 d][8 f]
#pragma unroll
    for (int i = 0; i < 32; i++) acc[i] = 0ull;

    const float*  Kp    = g_K + (size_t)p * D_ * D_;
    const float2* xbase = g_bufA + (size_t)(p*128) * FP_ + f0;

    for (int c = 0; c < 128; c += KT_) {
        // K chunk: 4096 floats = 1024 float4; 256 threads -> 4 each (linear)
        {
            const float4* src = (const float4*)(Kp + c*128);
            float4* dst = (float4*)&Ks[0][0];
#pragma unroll
            for (int i = 0; i < 4; i++) dst[tid + 256*i] = src[tid + 256*i];
        }
        // X chunk: 32 rows x 32 float4 = 1024 float4 -> 4 each
#pragma unroll
        for (int i = 0; i < 4; i++) {
            int lin = tid + 256*i;
            int kk = lin >> 5, c4 = lin & 31;
            const float4* s = (const float4*)(xbase + (size_t)(c + kk) * FP_);
            ((float4*)&Xs[kk][0])[c4] = s[c4];
        }
        __syncthreads();
#pragma unroll 4
        for (int kk = 0; kk < KT_; kk++) {
            float4 ka = *(const float4*)&Ks[kk][lane*4];            // per-lane, conflict-free
            const ulonglong2* xp = (const ulonglong2*)&Xs[kk][w*8]; // warp-uniform broadcast
            ulonglong2 x01 = xp[0], x23 = xp[1], x45 = xp[2], x67 = xp[3];
            unsigned long long xv[8] = {x01.x, x01.y, x23.x, x23.y, x45.x, x45.y, x67.x, x67.y};
            unsigned long long kp[4] = {pk2(ka.x), pk2(ka.y), pk2(ka.z), pk2(ka.w)};
#pragma unroll
            for (int i = 0; i < 4; i++)
#pragma unroll
                for (int j = 0; j < 8; j++)
                    acc[i*8 + j] = fma2(kp[i], xv[j], acc[i*8 + j]);
        }
        __syncthreads();
    }

    int rowb = p*128 + lane*4;
#pragma unroll
    for (int i = 0; i < 4; i++) {
        int row = rowb + i;
        float dist = avg_dist[row];
        float b = c_c32() * (dist * c_s32());
        float dec = __expf(c_kdec() * dist);
        float2* outp = g_bufB + (size_t)row*FP_ + f0 + w*8;
#pragma unroll
        for (int j = 0; j < 8; j += 2) {
            int f = f0 + w*8 + j;
            float ar0 = lo32(acc[i*8 + j]),   ai0 = hi32(acc[i*8 + j]);
            float ar1 = lo32(acc[i*8 + j+1]), ai1 = hi32(acc[i*8 + j+1]);
            float ss0, cc0; sc_big(b * (float)f, ss0, cc0);
            float ss1, cc1; sc_big(b * (float)(f+1), ss1, cc1);
            float pr0 = dec * cc0, pi0 = dec * ss0;
            float pr1 = dec * cc1, pi1 = dec * ss1;
            float4 st = make_float4(pr0*ar0 - pi0*ai0, pr0*ai0 + pi0*ar0,
                                    pr1*ar1 - pi1*ai1, pr1*ai1 + pi1*ar1);
            *(float4*)(outp + j) = st;
        }
    }
}

// f = 512 column only
__global__ void __launch_bounds__(128) k_gemm_last(const float* __restrict__ avg_dist) {
    __shared__ float2 xs[128];
    int p = blockIdx.x, d = threadIdx.x;
    xs[d] = g_bufA[(size_t)(p*128 + d)*FP_ + 512];
    __syncthreads();
    const float* Kp = g_K + (size_t)p * D_ * D_;
    float ar = 0.0f, ai = 0.0f;
#pragma unroll 8
    for (int e = 0; e < 128; e++) {
        float kv = Kp[e*128 + d];
        float2 x = xs[e];
        ar = fmaf(kv, x.x, ar);
        ai = fmaf(kv, x.y, ai);
    }
    int row = p*128 + d;
    float dist = avg_dist[row];
    float b = c_c32() * (dist * c_s32());
    float dec = __expf(c_kdec() * dist);
    float ss, cc; sc_big(b * 512.0f, ss, cc);
    float pr = dec * cc, pi = dec * ss;
    g_bufB[(size_t)row*FP_ + 512] = make_float2(pr*ar - pi*ai, pr*ai + pi*ar);
}

// ---------------- SpMM: bufA = A @ bufB, echo += w_rec*pf_rec*bufA ------------
// edge-outer, float4 gathers (2 f per load), 8 strips of 64 f in registers.
__global__ void __launch_bounds__(256) k_spmm(const float* __restrict__ rpos,
                                              const float* __restrict__ rcpos) {
    __shared__ __align__(16) float2 esh[8][520];
    int w = threadIdx.x >> 5, lane = threadIdx.x & 31;
    int row = blockIdx.x * 8 + w;
    int s = g_rowptr[row], e = g_rowptr[row+1];

    float4 acc[8];                        // (re0,im0,re1,im1) for f = k*64+lane*2
#pragma unroll
    for (int k = 0; k < 8; k++) acc[k] = make_float4(0.f, 0.f, 0.f, 0.f);
    float ar16 = 0.0f, ai16 = 0.0f;       // f = 512 (lane 0)

    for (int j = s; j < e; j++) {
        int cj = g_cols[j];
        float vj = g_vals[j];
        const float4* __restrict__ base = (const float4*)(g_bufB + (size_t)cj * FP_);
#pragma unroll
        for (int k = 0; k < 8; k++) {
            float4 t = base[k*32 + lane];
            acc[k].x = fmaf(vj, t.x, acc[k].x);
            acc[k].y = fmaf(vj, t.y, acc[k].y);
            acc[k].z = fmaf(vj, t.z, acc[k].z);
            acc[k].w = fmaf(vj, t.w, acc[k].w);
        }
        if (lane == 0) {
            float2 t = g_bufB[(size_t)cj*FP_ + 512];
            ar16 = fmaf(vj, t.x, ar16);
            ai16 = fmaf(vj, t.y, ai16);
        }
    }

    float px = rpos[3*row+0], py = rpos[3*row+1], pz = rpos[3*row+2];
    float rx = px - rcpos[0], ry = py - rcpos[1], rz = pz - rcpos[2];
    float dr = sqrtf(rx*rx + ry*ry + rz*rz);
    float br = c_c32() * (dr * c_s32());
    float wamp = __expf(c_kdec() * dr) / (dr*dr + 0.001f);

    float4* outp = (float4*)(g_bufA + (size_t)row*FP_);
#pragma unroll
    for (int k = 0; k < 8; k++) {
        int f = k*64 + lane*2;
        outp[k*32 + lane] = acc[k];
        float s0, c0; sc_big(br * (float)f, s0, c0);
        float s1, c1; sc_big(br * (float)(f+1), s1, c1);
        float4 ev = make_float4(wamp * (c0*acc[k].x - s0*acc[k].y),
                                wamp * (c0*acc[k].y + s0*acc[k].x),
                                wamp * (c1*acc[k].z - s1*acc[k].w),
                                wamp * (c1*acc[k].w + s1*acc[k].z));
        *(float4*)&esh[w][f] = ev;
    }
    if (lane == 0) {
        g_bufA[(size_t)row*FP_ + 512] = make_float2(ar16, ai16);
        float s2, c2; sc_big(br * 512.0f, s2, c2);
        esh[w][512] = make_float2(wamp * (c2*ar16 - s2*ai16), wamp * (c2*ai16 + s2*ar16));
    }
    __syncthreads();
    for (int f = threadIdx.x; f < F_; f += 256) {
        float sr = 0.0f, si = 0.0f;
#pragma unroll
        for (int ww = 0; ww < 8; ww++) { sr += esh[ww][f].x; si += esh[ww][f].y; }
        atomicAdd(&g_echo[2*f  ], sr);
        atomicAdd(&g_echo[2*f+1], si);
    }
}

// ---------------- final: irfft(echo) / fsm_window -----------------------------
__global__ void __launch_bounds__(1024) k_ifft() {
    __shared__ float twc[T_], tws[T_];
    __shared__ float2 es[32];
    int t = threadIdx.x, b = blockIdx.x;
    {
        float th = (float)(2.0*3.14159265358979323846/1024.0) * (float)t;
        float s, c; __sincosf(th, &s, &c);
        twc[t] = c; tws[t] = s;
    }
    if (t < 32) {
        int k = b*32 + 1 + t;
        float2 v = make_float2(g_echo[2*k], g_echo[2*k+1]);
        if (k == 512) { v.x *= 0.5f; v.y *= 0.5f; }
        es[t] = v;
    }
    __syncthreads();
    float sum = 0.0f;
#pragma unroll 8
    for (int i = 0; i < 32; i++) {
        int k = b*32 + 1 + i;
        int m = (k * t) & 1023;
        float2 X = es[i];
        sum = fmaf(2.0f * X.x, twc[m], sum);
        sum = fmaf(-2.0f * X.y, tws[m], sum);
    }
    atomicAdd(&g_time[t], sum);
}

__global__ void __launch_bounds__(1024) k_scale(float* __restrict__ out) {
    int t = threadIdx.x;
    float v = (g_time[t] + g_echo[0]) * (1.0f / 1024.0f);
    float ta = (float)t / 16000.0f;
    float fsm = __expf(LOG_GAMMA_F * ta);
    out[t] = v / fsm;
}

// ---------------- launcher ----------------------------------------------------
extern "C" void kernel_launch(void* const* d_in, const int* in_sizes, int n_in,
                              void* d_out, int out_size) {
    const float* spos  = (const float*)d_in[0];
    const float* rcpos = (const float*)d_in[1];
    const float* absorb= (const float*)d_in[2];
    const float* scat  = (const float*)d_in[3];
    const float* gkv   = (const float*)d_in[4];
    const float* basis = (const float*)d_in[5];
    const float* avg   = (const float*)d_in[6];
    const float* rpos  = (const float*)d_in[7];
    const int*   gkr   = (const int*)d_in[8];
    const int*   gkc   = (const int*)d_in[9];
    const int*   obj   = (const int*)d_in[10];

    // Order chosen so launch #4 (what ncu -s captures) is the heavy k_gemm.
    k_buildKzero<<<(P_*D_*D_ + 255)/256, 256>>>(basis, absorb, scat, obj);  // 1
    k_hist<<<E_/256, 256>>>(gkr);                                           // 2
    k_rad<<<R_/8, 256>>>(rpos, spos, rcpos);                                // 3
    k_gemm<<<dim3(P_, 8), 256>>>(avg);                                      // 4  <- profile target
    k_scan<<<1, 1024>>>();                                                  // 5
    k_scatter<<<E_/256, 256>>>(gkr, gkc, gkv);                              // 6
    k_gemm_last<<<P_, 128>>>(avg);                                          // 7
    k_spmm<<<R_/8, 256>>>(rpos, rcpos);                                     // 8
    for (int b = 1; b < 4; b++) {
        k_gemm<<<dim3(P_, 8), 256>>>(avg);
        k_gemm_last<<<P_, 128>>>(avg);
        k_spmm<<<R_/8, 256>>>(rpos, rcpos);
    }
    k_ifft<<<16, 1024>>>();
    k_scale<<<1, 1024>>>((float*)d_out);
}